// round 2
// baseline (speedup 1.0000x reference)
#include <cuda_runtime.h>
#include <cstdint>
#include <math.h>

// Problem constants (from reference): B=128 episodes, L=512 pad, D=512 dims.
#define NB 128
#define NL 512
#define ND 512
#define TILE 16
#define ITMAX 64
#define CG_TOL 1e-6f

// Scratch (__device__ globals; no allocations allowed)
__device__ int   g_sup_idx[NB][NL];
__device__ int   g_sup_lab[NB][NL];
__device__ int   g_qry_idx[NB][NL];
__device__ int   g_cnt[NB][4];        // [0]=ns, [1]=np, [2]=nq
__device__ float g_mu[NB][3][ND];     // task, pos, neg means
__device__ float g_rr[NB][2][ND];     // r_pos, r_neg  (= M^{-1} @ 1)
__device__ float g_sc[NB][4];         // mu_p·r_p, sum(mu_p), mu_n·r_n, sum(mu_n)

// ---------------------------------------------------------------------------
// Kernel 1: segmentation. batch_index is sorted, so each episode is a
// contiguous range; stable split into support/query preserving order.
// One warp per episode, ballot-based rank computation.
// ---------------------------------------------------------------------------
__global__ void seg_kernel(const int* __restrict__ bidx, const int* __restrict__ isq,
                           const int* __restrict__ labels, int N) {
  int b = blockIdx.x;
  int lane = threadIdx.x;
  int start = 0, end = 0;
  if (lane == 0) {
    int lo = 0, hi = N;
    while (lo < hi) { int m = (lo + hi) >> 1; if (bidx[m] < b) lo = m + 1; else hi = m; }
    start = lo; hi = N;
    while (lo < hi) { int m = (lo + hi) >> 1; if (bidx[m] <= b) lo = m + 1; else hi = m; }
    end = lo;
  }
  start = __shfl_sync(0xffffffffu, start, 0);
  end   = __shfl_sync(0xffffffffu, end, 0);

  int sbase = 0, qbase = 0, pcnt = 0;
  for (int k0 = start; k0 < end; k0 += 32) {
    int k = k0 + lane;
    bool valid = k < end;
    int q  = valid ? isq[k]    : 0;
    int lb = valid ? labels[k] : 0;
    unsigned mq = __ballot_sync(0xffffffffu, valid && q != 0);
    unsigned ms = __ballot_sync(0xffffffffu, valid && q == 0);
    unsigned mp = __ballot_sync(0xffffffffu, valid && q == 0 && lb != 0);
    unsigned lt = (1u << lane) - 1u;
    if (valid) {
      if (q != 0) {
        int r = qbase + __popc(mq & lt);
        if (r < NL) g_qry_idx[b][r] = k;
      } else {
        int r = sbase + __popc(ms & lt);
        if (r < NL) { g_sup_idx[b][r] = k; g_sup_lab[b][r] = lb; }
      }
    }
    qbase += __popc(mq); sbase += __popc(ms); pcnt += __popc(mp);
  }
  if (lane == 0) {
    g_cnt[b][0] = min(sbase, NL);
    g_cnt[b][1] = pcnt;
    g_cnt[b][2] = min(qbase, NL);
  }
}

// ---------------------------------------------------------------------------
// Kernel 2: per-episode means (task / pos / neg). One CTA per episode,
// thread d owns dimension d; coalesced row reads. Also warms L2 with the
// support rows the CG kernel will re-read.
// ---------------------------------------------------------------------------
__global__ void mean_kernel(const float* __restrict__ X) {
  int b = blockIdx.x, d = threadIdx.x;
  int ns = g_cnt[b][0], np = g_cnt[b][1];
  float s = 0.f, sp = 0.f;
  for (int j = 0; j < ns; j++) {
    int idx = g_sup_idx[b][j];
    int lb  = g_sup_lab[b][j];
    float v = X[(size_t)idx * ND + d];
    s += v;
    if (lb) sp += v;
  }
  g_mu[b][0][d] = s / (float)ns;
  g_mu[b][1][d] = sp / (float)np;
  g_mu[b][2][d] = (s - sp) / (float)(ns - np);
}

// ---------------------------------------------------------------------------
// Block reduction of 4 values across 512 threads. Result broadcast to all.
// ---------------------------------------------------------------------------
__device__ __forceinline__ void red4(float* s_red, float v0, float v1, float v2, float v3,
                                     float* out) {
  #pragma unroll
  for (int o = 16; o; o >>= 1) {
    v0 += __shfl_down_sync(0xffffffffu, v0, o);
    v1 += __shfl_down_sync(0xffffffffu, v1, o);
    v2 += __shfl_down_sync(0xffffffffu, v2, o);
    v3 += __shfl_down_sync(0xffffffffu, v3, o);
  }
  int t = threadIdx.x, w = t >> 5, l = t & 31;
  if (l == 0) {
    s_red[w * 4 + 0] = v0; s_red[w * 4 + 1] = v1;
    s_red[w * 4 + 2] = v2; s_red[w * 4 + 3] = v3;
  }
  __syncthreads();
  if (t < 4) {
    float s = 0.f;
    #pragma unroll
    for (int i = 0; i < 16; i++) s += s_red[i * 4 + t];
    s_red[64 + t] = s;
  }
  __syncthreads();
  out[0] = s_red[64]; out[1] = s_red[65]; out[2] = s_red[66]; out[3] = s_red[67];
  __syncthreads();
}

// ---------------------------------------------------------------------------
// Kernel 3: fused CG for both class systems per episode.
//   M_c v = wt*Sum_j x_j(x_j.v) + wc*Sum_{j in c} x_j(x_j.v)
//           - wmt*(mu_t.v)mu_t - wmc*(mu_c.v)mu_c + 0.1 v
// Matrix-free: per iteration, stream support rows through a double-buffered
// cp.async smem tile (read from L2 once per iteration, shared by both systems).
// Pass 1: 16 warps compute per-row dots d_j = x_j.p (both systems).
// Pass 2: thread d accumulates Ap[d] += c_j d_j x_j[d] (coalesced smem).
// CG state vectors are register-resident (thread d owns component d).
// ---------------------------------------------------------------------------
#define CG_SMEM_BYTES ((2*TILE*ND + 2*ND + 2*TILE + 2*NL + NL + 80) * 4)

__global__ __launch_bounds__(512, 1) void cg_kernel(const float* __restrict__ X) {
  extern __shared__ float smem[];
  float* sT   = smem;                    // [2][TILE][ND] tile buffers
  float* s_pp = sT + 2 * TILE * ND;      // [ND]
  float* s_pn = s_pp + ND;               // [ND]
  float* s_ep = s_pn + ND;               // [TILE]
  float* s_en = s_ep + TILE;             // [TILE]
  float* s_cp = s_en + TILE;             // [NL] per-row coef (pos system)
  float* s_cn = s_cp + NL;               // [NL] per-row coef (neg system)
  int*   s_idx = (int*)(s_cn + NL);      // [NL]
  float* s_red = (float*)(s_idx + NL);   // [80]

  int b = blockIdx.x, tid = threadIdx.x, lane = tid & 31, w = tid >> 5;
  int ns = g_cnt[b][0], np = g_cnt[b][1];
  float fns = (float)ns, fnp = (float)np, fnn = (float)(ns - np);
  float wt  = 0.9f / (fns - 1.f), wmt = 0.9f * fns / (fns - 1.f);
  float wp  = 0.1f / (fnp - 1.f), wmp = 0.1f * fnp / (fnp - 1.f);
  float wn  = 0.1f / (fnn - 1.f), wmn = 0.1f * fnn / (fnn - 1.f);

  for (int j = tid; j < ns; j += 512) {
    s_idx[j] = g_sup_idx[b][j];
    int lb = g_sup_lab[b][j];
    s_cp[j] = wt + (lb ? wp : 0.f);
    s_cn[j] = wt + (lb ? 0.f : wn);
  }
  float mt  = g_mu[b][0][tid];
  float mp_ = g_mu[b][1][tid];
  float mn_ = g_mu[b][2][tid];
  // CG state (per-thread component): solve M x = 1 for pos & neg systems
  float xp = 0.f, xn = 0.f, rp = 1.f, rn = 1.f, pp = 1.f, pn = 1.f;
  float rsp = (float)ND, rsn = (float)ND;
  __syncthreads();

  int ntiles = (ns + TILE - 1) / TILE;
  int col4  = tid & 127;   // float4 column within row
  int rbase = tid >> 7;    // row group 0..3
  float o4[4];

  for (int it = 0; it < ITMAX; ++it) {
    // publish search direction + mean dot products
    s_pp[tid] = pp; s_pn[tid] = pn;
    red4(s_red, mt * pp, mp_ * pp, mt * pn, mn_ * pn, o4);
    float dtp = o4[0], dpp = o4[1], dtn = o4[2], dnn = o4[3];

    // pass-1 p slices in registers (each thread reads p[lane+32k])
    float ppr[TILE], pnr[TILE];
    #pragma unroll
    for (int k = 0; k < TILE; k++) { ppr[k] = s_pp[lane + 32 * k]; pnr[k] = s_pn[lane + 32 * k]; }

    float apr = 0.f, anr = 0.f;

    // prologue: async-load tile 0 into buffer 0
    {
      int tr0 = min(TILE, ns);
      #pragma unroll
      for (int s5 = 0; s5 < 4; s5++) {
        int r = rbase + s5 * 4;
        if (r < tr0) {
          int gj = s_idx[r];
          const float* src = X + (size_t)gj * ND + col4 * 4;
          unsigned dst = (unsigned)__cvta_generic_to_shared(&sT[r * ND + col4 * 4]);
          asm volatile("cp.async.cg.shared.global [%0], [%1], 16;" :: "r"(dst), "l"(src));
        }
      }
      asm volatile("cp.async.commit_group;");
    }

    for (int t = 0; t < ntiles; t++) {
      int buf = t & 1;
      if (t + 1 < ntiles) {
        int j0 = (t + 1) * TILE;
        int trn = min(TILE, ns - j0);
        int bufn = (t + 1) & 1;
        #pragma unroll
        for (int s5 = 0; s5 < 4; s5++) {
          int r = rbase + s5 * 4;
          if (r < trn) {
            int gj = s_idx[j0 + r];
            const float* src = X + (size_t)gj * ND + col4 * 4;
            unsigned dst = (unsigned)__cvta_generic_to_shared(&sT[bufn * TILE * ND + r * ND + col4 * 4]);
            asm volatile("cp.async.cg.shared.global [%0], [%1], 16;" :: "r"(dst), "l"(src));
          }
        }
      }
      asm volatile("cp.async.commit_group;");   // possibly-empty group keeps wait uniform
      asm volatile("cp.async.wait_group 1;");
      __syncthreads();

      int tr = min(TILE, ns - t * TILE);
      // pass 1: warp w -> row w dot products for both systems
      if (w < tr) {
        const float* row = &sT[buf * TILE * ND + w * ND];
        float ap = 0.f, an = 0.f;
        #pragma unroll
        for (int k = 0; k < TILE; k++) {
          float v = row[lane + 32 * k];
          ap += v * ppr[k]; an += v * pnr[k];
        }
        #pragma unroll
        for (int o = 16; o; o >>= 1) {
          ap += __shfl_down_sync(0xffffffffu, ap, o);
          an += __shfl_down_sync(0xffffffffu, an, o);
        }
        if (lane == 0) {
          int j = t * TILE + w;
          s_ep[w] = s_cp[j] * ap;
          s_en[w] = s_cn[j] * an;
        }
      }
      __syncthreads();
      // pass 2: thread d accumulates weighted rows (coalesced smem)
      const float* colp = &sT[buf * TILE * ND + tid];
      if (tr == TILE) {
        #pragma unroll
        for (int r2 = 0; r2 < TILE; r2++) {
          float v = colp[r2 * ND];
          apr += s_ep[r2] * v; anr += s_en[r2] * v;
        }
      } else {
        for (int r2 = 0; r2 < tr; r2++) {
          float v = colp[r2 * ND];
          apr += s_ep[r2] * v; anr += s_en[r2] * v;
        }
      }
      __syncthreads();
    }

    // rank-1 mean corrections + ridge
    float Ap_p = apr + 0.1f * pp - wmt * dtp * mt - wmp * dpp * mp_;
    float Ap_n = anr + 0.1f * pn - wmt * dtn * mt - wmn * dnn * mn_;

    red4(s_red, pp * Ap_p, pn * Ap_n, 0.f, 0.f, o4);
    float alp = rsp / o4[0], aln = rsn / o4[1];
    xp += alp * pp;  rp -= alp * Ap_p;
    xn += aln * pn;  rn -= aln * Ap_n;

    red4(s_red, rp * rp, rn * rn, 0.f, 0.f, o4);
    float bp = o4[0] / rsp, bn = o4[1] / rsn;
    rsp = o4[0]; rsn = o4[1];
    pp = rp + bp * pp;
    pn = rn + bn * pn;
    if (rsp < CG_TOL && rsn < CG_TOL) break;   // uniform across CTA
  }

  g_rr[b][0][tid] = xp;
  g_rr[b][1][tid] = xn;
  red4(s_red, mp_ * xp, mp_, mn_ * xn, mn_, o4);
  if (tid == 0) {
    g_sc[b][0] = o4[0]; g_sc[b][1] = o4[1];
    g_sc[b][2] = o4[2]; g_sc[b][3] = o4[3];
  }
}

// ---------------------------------------------------------------------------
// Kernel 4: outputs. maha = (q·r - mu·r) * (sum(q) - sum(mu)); warp per query
// row; zero-fill masked rows (output is poisoned 0xAA before timing).
// ---------------------------------------------------------------------------
__global__ void out_kernel(const float* __restrict__ X, const float* __restrict__ log_scale,
                           float* __restrict__ out) {
  __shared__ float s_rp[ND];
  __shared__ float s_rn[ND];
  __shared__ float s_s[8];
  int b = blockIdx.x, tid = threadIdx.x;
  for (int i = tid; i < ND; i += 256) { s_rp[i] = g_rr[b][0][i]; s_rn[i] = g_rr[b][1][i]; }
  if (tid < 4) s_s[tid] = g_sc[b][tid];
  if (tid == 4) s_s[4] = expf(log_scale[0]);
  __syncthreads();
  int nq = g_cnt[b][2];
  int w = tid >> 5, lane = tid & 31;
  for (int i = w; i < NL; i += 8) {
    if (i < nq) {
      int gj = g_qry_idx[b][i];
      const float* q = X + (size_t)gj * ND;
      float aqr = 0.f, aqn = 0.f, aqs = 0.f;
      #pragma unroll
      for (int k = 0; k < 16; k++) {
        float v = q[lane + 32 * k];
        aqr += v * s_rp[lane + 32 * k];
        aqn += v * s_rn[lane + 32 * k];
        aqs += v;
      }
      #pragma unroll
      for (int o = 16; o; o >>= 1) {
        aqr += __shfl_down_sync(0xffffffffu, aqr, o);
        aqn += __shfl_down_sync(0xffffffffu, aqn, o);
        aqs += __shfl_down_sync(0xffffffffu, aqs, o);
      }
      if (lane == 0) {
        float sc = s_s[4];
        float sp = aqr - s_s[0], tp = aqs - s_s[1];
        float sn = aqn - s_s[2], tn = aqs - s_s[3];
        size_t o0 = ((size_t)b * NL + i) * 2;
        out[o0]     = sn * tn * sc;   // neg logit
        out[o0 + 1] = sp * tp * sc;   // pos logit
      }
    } else if (lane == 0) {
      size_t o0 = ((size_t)b * NL + i) * 2;
      out[o0] = 0.f; out[o0 + 1] = 0.f;
    }
  }
}

// ---------------------------------------------------------------------------
// Inputs (metadata order): graph_reprs f32[N*512], log_scale f32[1],
// labels i32[N], is_query i32[N], batch_index i32[N] (sorted).
// Output: f32[128*512*2].
// ---------------------------------------------------------------------------
extern "C" void kernel_launch(void* const* d_in, const int* in_sizes, int n_in,
                              void* d_out, int out_size) {
  const float* X      = (const float*)d_in[0];
  const float* logsc  = (const float*)d_in[1];
  const int*   labels = (const int*)d_in[2];
  const int*   isq    = (const int*)d_in[3];
  const int*   bidx   = (const int*)d_in[4];
  int N = in_sizes[2];

  cudaFuncSetAttribute(cg_kernel, cudaFuncAttributeMaxDynamicSharedMemorySize, CG_SMEM_BYTES);

  seg_kernel<<<NB, 32>>>(bidx, isq, labels, N);
  mean_kernel<<<NB, ND>>>(X);
  cg_kernel<<<NB, ND, CG_SMEM_BYTES>>>(X);
  out_kernel<<<NB, 256>>>(X, logsc, (float*)d_out);
}

// round 3
// speedup vs baseline: 1.0149x; 1.0149x over previous
#include <cuda_runtime.h>
#include <cstdint>
#include <math.h>

// Problem constants (from reference): B=128 episodes, L=512 pad, D=512 dims.
#define NB 128
#define NL 512
#define ND 512
#define TILE 16
#define ITMAX 64
#define CG_TOL 1e-6f

// Scratch (__device__ globals; no allocations allowed)
__device__ int   g_sup_idx[NB][NL];
__device__ int   g_sup_lab[NB][NL];
__device__ int   g_qry_idx[NB][NL];
__device__ int   g_cnt[NB][4];        // [0]=ns, [1]=np, [2]=nq
__device__ float g_mu[NB][3][ND];     // task, pos, neg means
__device__ float g_rr[NB][2][ND];     // r_pos, r_neg  (= M^{-1} @ 1)
__device__ float g_sc[NB][4];         // mu_p·r_p, sum(mu_p), mu_n·r_n, sum(mu_n)

// ---------------------------------------------------------------------------
// Kernel 1: segmentation. batch_index is sorted, so each episode is a
// contiguous range; stable split into support/query preserving order.
// One warp per episode, ballot-based rank computation.
// ---------------------------------------------------------------------------
__global__ void seg_kernel(const int* __restrict__ bidx, const int* __restrict__ isq,
                           const int* __restrict__ labels, int N) {
  int b = blockIdx.x;
  int lane = threadIdx.x;
  int start = 0, end = 0;
  if (lane == 0) {
    int lo = 0, hi = N;
    while (lo < hi) { int m = (lo + hi) >> 1; if (bidx[m] < b) lo = m + 1; else hi = m; }
    start = lo; hi = N;
    while (lo < hi) { int m = (lo + hi) >> 1; if (bidx[m] <= b) lo = m + 1; else hi = m; }
    end = lo;
  }
  start = __shfl_sync(0xffffffffu, start, 0);
  end   = __shfl_sync(0xffffffffu, end, 0);

  int sbase = 0, qbase = 0, pcnt = 0;
  for (int k0 = start; k0 < end; k0 += 32) {
    int k = k0 + lane;
    bool valid = k < end;
    int q  = valid ? isq[k]    : 0;
    int lb = valid ? labels[k] : 0;
    unsigned mq = __ballot_sync(0xffffffffu, valid && q != 0);
    unsigned ms = __ballot_sync(0xffffffffu, valid && q == 0);
    unsigned mp = __ballot_sync(0xffffffffu, valid && q == 0 && lb != 0);
    unsigned lt = (1u << lane) - 1u;
    if (valid) {
      if (q != 0) {
        int r = qbase + __popc(mq & lt);
        if (r < NL) g_qry_idx[b][r] = k;
      } else {
        int r = sbase + __popc(ms & lt);
        if (r < NL) { g_sup_idx[b][r] = k; g_sup_lab[b][r] = lb; }
      }
    }
    qbase += __popc(mq); sbase += __popc(ms); pcnt += __popc(mp);
  }
  if (lane == 0) {
    g_cnt[b][0] = min(sbase, NL);
    g_cnt[b][1] = pcnt;
    g_cnt[b][2] = min(qbase, NL);
  }
}

// ---------------------------------------------------------------------------
// Kernel 2: per-episode means (task / pos / neg). One CTA per episode,
// thread d owns dimension d; coalesced row reads. Also warms L2 with the
// support rows the CG kernel will re-read.
// ---------------------------------------------------------------------------
__global__ void mean_kernel(const float* __restrict__ X) {
  int b = blockIdx.x, d = threadIdx.x;
  int ns = g_cnt[b][0], np = g_cnt[b][1];
  float s = 0.f, sp = 0.f;
  for (int j = 0; j < ns; j++) {
    int idx = g_sup_idx[b][j];
    int lb  = g_sup_lab[b][j];
    float v = X[(size_t)idx * ND + d];
    s += v;
    if (lb) sp += v;
  }
  g_mu[b][0][d] = s / (float)ns;
  g_mu[b][1][d] = sp / (float)np;
  g_mu[b][2][d] = (s - sp) / (float)(ns - np);
}

// ---------------------------------------------------------------------------
// Block reduction of 4 values across 512 threads. Result broadcast to all.
// ---------------------------------------------------------------------------
__device__ __forceinline__ void red4(float* s_red, float v0, float v1, float v2, float v3,
                                     float* out) {
  #pragma unroll
  for (int o = 16; o; o >>= 1) {
    v0 += __shfl_down_sync(0xffffffffu, v0, o);
    v1 += __shfl_down_sync(0xffffffffu, v1, o);
    v2 += __shfl_down_sync(0xffffffffu, v2, o);
    v3 += __shfl_down_sync(0xffffffffu, v3, o);
  }
  int t = threadIdx.x, w = t >> 5, l = t & 31;
  if (l == 0) {
    s_red[w * 4 + 0] = v0; s_red[w * 4 + 1] = v1;
    s_red[w * 4 + 2] = v2; s_red[w * 4 + 3] = v3;
  }
  __syncthreads();
  if (t < 4) {
    float s = 0.f;
    #pragma unroll
    for (int i = 0; i < 16; i++) s += s_red[i * 4 + t];
    s_red[64 + t] = s;
  }
  __syncthreads();
  out[0] = s_red[64]; out[1] = s_red[65]; out[2] = s_red[66]; out[3] = s_red[67];
  __syncthreads();
}

// ---------------------------------------------------------------------------
// Kernel 3: fused CG for both class systems per episode.
//   M_c v = wt*Sum_j x_j(x_j.v) + wc*Sum_{j in c} x_j(x_j.v)
//           - wmt*(mu_t.v)mu_t - wmc*(mu_c.v)mu_c + 0.1 v
// Matrix-free: per iteration, stream support rows through a double-buffered
// cp.async smem tile (read from L2 once per iteration, shared by both systems).
// Pass 1: 16 warps compute per-row dots d_j = x_j.p (both systems).
// Pass 2: thread d accumulates Ap[d] += c_j d_j x_j[d] (coalesced smem).
// CG state vectors are register-resident (thread d owns component d).
// ---------------------------------------------------------------------------
#define CG_SMEM_BYTES ((2*TILE*ND + 2*ND + 2*TILE + 2*NL + NL + 80) * 4)

__global__ __launch_bounds__(512, 1) void cg_kernel(const float* __restrict__ X) {
  extern __shared__ float smem[];
  float* sT   = smem;                    // [2][TILE][ND] tile buffers
  float* s_pp = sT + 2 * TILE * ND;      // [ND]
  float* s_pn = s_pp + ND;               // [ND]
  float* s_ep = s_pn + ND;               // [TILE]
  float* s_en = s_ep + TILE;             // [TILE]
  float* s_cp = s_en + TILE;             // [NL] per-row coef (pos system)
  float* s_cn = s_cp + NL;               // [NL] per-row coef (neg system)
  int*   s_idx = (int*)(s_cn + NL);      // [NL]
  float* s_red = (float*)(s_idx + NL);   // [80]

  int b = blockIdx.x, tid = threadIdx.x, lane = tid & 31, w = tid >> 5;
  int ns = g_cnt[b][0], np = g_cnt[b][1];
  float fns = (float)ns, fnp = (float)np, fnn = (float)(ns - np);
  float wt  = 0.9f / (fns - 1.f), wmt = 0.9f * fns / (fns - 1.f);
  float wp  = 0.1f / (fnp - 1.f), wmp = 0.1f * fnp / (fnp - 1.f);
  float wn  = 0.1f / (fnn - 1.f), wmn = 0.1f * fnn / (fnn - 1.f);

  for (int j = tid; j < ns; j += 512) {
    s_idx[j] = g_sup_idx[b][j];
    int lb = g_sup_lab[b][j];
    s_cp[j] = wt + (lb ? wp : 0.f);
    s_cn[j] = wt + (lb ? 0.f : wn);
  }
  float mt  = g_mu[b][0][tid];
  float mp_ = g_mu[b][1][tid];
  float mn_ = g_mu[b][2][tid];
  // CG state (per-thread component): solve M x = 1 for pos & neg systems
  float xp = 0.f, xn = 0.f, rp = 1.f, rn = 1.f, pp = 1.f, pn = 1.f;
  float rsp = (float)ND, rsn = (float)ND;
  __syncthreads();

  int ntiles = (ns + TILE - 1) / TILE;
  int col4  = tid & 127;   // float4 column within row
  int rbase = tid >> 7;    // row group 0..3
  float o4[4];

  for (int it = 0; it < ITMAX; ++it) {
    // publish search direction + mean dot products
    s_pp[tid] = pp; s_pn[tid] = pn;
    red4(s_red, mt * pp, mp_ * pp, mt * pn, mn_ * pn, o4);
    float dtp = o4[0], dpp = o4[1], dtn = o4[2], dnn = o4[3];

    // pass-1 p slices in registers (each thread reads p[lane+32k])
    float ppr[TILE], pnr[TILE];
    #pragma unroll
    for (int k = 0; k < TILE; k++) { ppr[k] = s_pp[lane + 32 * k]; pnr[k] = s_pn[lane + 32 * k]; }

    float apr = 0.f, anr = 0.f;

    // prologue: async-load tile 0 into buffer 0
    {
      int tr0 = min(TILE, ns);
      #pragma unroll
      for (int s5 = 0; s5 < 4; s5++) {
        int r = rbase + s5 * 4;
        if (r < tr0) {
          int gj = s_idx[r];
          const float* src = X + (size_t)gj * ND + col4 * 4;
          unsigned dst = (unsigned)__cvta_generic_to_shared(&sT[r * ND + col4 * 4]);
          asm volatile("cp.async.cg.shared.global [%0], [%1], 16;" :: "r"(dst), "l"(src));
        }
      }
      asm volatile("cp.async.commit_group;");
    }

    for (int t = 0; t < ntiles; t++) {
      int buf = t & 1;
      if (t + 1 < ntiles) {
        int j0 = (t + 1) * TILE;
        int trn = min(TILE, ns - j0);
        int bufn = (t + 1) & 1;
        #pragma unroll
        for (int s5 = 0; s5 < 4; s5++) {
          int r = rbase + s5 * 4;
          if (r < trn) {
            int gj = s_idx[j0 + r];
            const float* src = X + (size_t)gj * ND + col4 * 4;
            unsigned dst = (unsigned)__cvta_generic_to_shared(&sT[bufn * TILE * ND + r * ND + col4 * 4]);
            asm volatile("cp.async.cg.shared.global [%0], [%1], 16;" :: "r"(dst), "l"(src));
          }
        }
      }
      asm volatile("cp.async.commit_group;");   // possibly-empty group keeps wait uniform
      asm volatile("cp.async.wait_group 1;");
      __syncthreads();

      int tr = min(TILE, ns - t * TILE);
      // pass 1: warp w -> row w dot products for both systems
      if (w < tr) {
        const float* row = &sT[buf * TILE * ND + w * ND];
        float ap = 0.f, an = 0.f;
        #pragma unroll
        for (int k = 0; k < TILE; k++) {
          float v = row[lane + 32 * k];
          ap += v * ppr[k]; an += v * pnr[k];
        }
        #pragma unroll
        for (int o = 16; o; o >>= 1) {
          ap += __shfl_down_sync(0xffffffffu, ap, o);
          an += __shfl_down_sync(0xffffffffu, an, o);
        }
        if (lane == 0) {
          int j = t * TILE + w;
          s_ep[w] = s_cp[j] * ap;
          s_en[w] = s_cn[j] * an;
        }
      }
      __syncthreads();
      // pass 2: thread d accumulates weighted rows (coalesced smem)
      const float* colp = &sT[buf * TILE * ND + tid];
      if (tr == TILE) {
        #pragma unroll
        for (int r2 = 0; r2 < TILE; r2++) {
          float v = colp[r2 * ND];
          apr += s_ep[r2] * v; anr += s_en[r2] * v;
        }
      } else {
        for (int r2 = 0; r2 < tr; r2++) {
          float v = colp[r2 * ND];
          apr += s_ep[r2] * v; anr += s_en[r2] * v;
        }
      }
      __syncthreads();
    }

    // rank-1 mean corrections + ridge
    float Ap_p = apr + 0.1f * pp - wmt * dtp * mt - wmp * dpp * mp_;
    float Ap_n = anr + 0.1f * pn - wmt * dtn * mt - wmn * dnn * mn_;

    red4(s_red, pp * Ap_p, pn * Ap_n, 0.f, 0.f, o4);
    float alp = rsp / o4[0], aln = rsn / o4[1];
    xp += alp * pp;  rp -= alp * Ap_p;
    xn += aln * pn;  rn -= aln * Ap_n;

    red4(s_red, rp * rp, rn * rn, 0.f, 0.f, o4);
    float bp = o4[0] / rsp, bn = o4[1] / rsn;
    rsp = o4[0]; rsn = o4[1];
    pp = rp + bp * pp;
    pn = rn + bn * pn;
    if (rsp < CG_TOL && rsn < CG_TOL) break;   // uniform across CTA
  }

  g_rr[b][0][tid] = xp;
  g_rr[b][1][tid] = xn;
  red4(s_red, mp_ * xp, mp_, mn_ * xn, mn_, o4);
  if (tid == 0) {
    g_sc[b][0] = o4[0]; g_sc[b][1] = o4[1];
    g_sc[b][2] = o4[2]; g_sc[b][3] = o4[3];
  }
}

// ---------------------------------------------------------------------------
// Kernel 4: outputs. maha = (q·r - mu·r) * (sum(q) - sum(mu)); warp per query
// row; zero-fill masked rows (output is poisoned 0xAA before timing).
// ---------------------------------------------------------------------------
__global__ void out_kernel(const float* __restrict__ X, const float* __restrict__ log_scale,
                           float* __restrict__ out) {
  __shared__ float s_rp[ND];
  __shared__ float s_rn[ND];
  __shared__ float s_s[8];
  int b = blockIdx.x, tid = threadIdx.x;
  for (int i = tid; i < ND; i += 256) { s_rp[i] = g_rr[b][0][i]; s_rn[i] = g_rr[b][1][i]; }
  if (tid < 4) s_s[tid] = g_sc[b][tid];
  if (tid == 4) s_s[4] = expf(log_scale[0]);
  __syncthreads();
  int nq = g_cnt[b][2];
  int w = tid >> 5, lane = tid & 31;
  for (int i = w; i < NL; i += 8) {
    if (i < nq) {
      int gj = g_qry_idx[b][i];
      const float* q = X + (size_t)gj * ND;
      float aqr = 0.f, aqn = 0.f, aqs = 0.f;
      #pragma unroll
      for (int k = 0; k < 16; k++) {
        float v = q[lane + 32 * k];
        aqr += v * s_rp[lane + 32 * k];
        aqn += v * s_rn[lane + 32 * k];
        aqs += v;
      }
      #pragma unroll
      for (int o = 16; o; o >>= 1) {
        aqr += __shfl_down_sync(0xffffffffu, aqr, o);
        aqn += __shfl_down_sync(0xffffffffu, aqn, o);
        aqs += __shfl_down_sync(0xffffffffu, aqs, o);
      }
      if (lane == 0) {
        float sc = s_s[4];
        float sp = aqr - s_s[0], tp = aqs - s_s[1];
        float sn = aqn - s_s[2], tn = aqs - s_s[3];
        size_t o0 = ((size_t)b * NL + i) * 2;
        out[o0]     = sn * tn * sc;   // neg logit
        out[o0 + 1] = sp * tp * sc;   // pos logit
      }
    } else if (lane == 0) {
      size_t o0 = ((size_t)b * NL + i) * 2;
      out[o0] = 0.f; out[o0 + 1] = 0.f;
    }
  }
}

// ---------------------------------------------------------------------------
// Inputs (metadata order): graph_reprs f32[N*512], log_scale f32[1],
// labels i32[N], is_query i32[N], batch_index i32[N] (sorted).
// Output: f32[128*512*2].
// ---------------------------------------------------------------------------
extern "C" void kernel_launch(void* const* d_in, const int* in_sizes, int n_in,
                              void* d_out, int out_size) {
  const float* X      = (const float*)d_in[0];
  const float* logsc  = (const float*)d_in[1];
  const int*   labels = (const int*)d_in[2];
  const int*   isq    = (const int*)d_in[3];
  const int*   bidx   = (const int*)d_in[4];
  int N = in_sizes[2];

  cudaFuncSetAttribute(cg_kernel, cudaFuncAttributeMaxDynamicSharedMemorySize, CG_SMEM_BYTES);

  seg_kernel<<<NB, 32>>>(bidx, isq, labels, N);
  mean_kernel<<<NB, ND>>>(X);
  cg_kernel<<<NB, ND, CG_SMEM_BYTES>>>(X);
  out_kernel<<<NB, 256>>>(X, logsc, (float*)d_out);
}